// round 4
// baseline (speedup 1.0000x reference)
#include <cuda_runtime.h>
#include <math.h>

// Problem constants
#define NNODES 50000
#define EMAX   400000
#define CCH    128
#define PI_F   3.14159265358979323846f
#define R_CUT_F 5.0f

// Scratch (static device arrays: no allocation allowed)
__device__ float g_h[NNODES * CCH];          // silu(s@W1+b1)
__device__ float g_spass[NNODES * 3 * CCH];  // s_pass
__device__ int   g_count[NNODES];            // degree counters / fill cursor
__device__ int   g_start[NNODES + 1];        // CSR offsets
__device__ int   g_eid[EMAX];                // edge ids grouped by dst
__device__ float g_basis[EMAX * 20];         // sin(n x) * fc / r  per edge
__device__ float g_fc[EMAX];                 // fcut per edge

// ---------------------------------------------------------------------------
// GEMM K=128 (unchanged from R2 — proven): 128x128 tile, 8x8 blocking.
// ---------------------------------------------------------------------------
__global__ void __launch_bounds__(256) gemm_v2(
    const float* __restrict__ A,
    const float* __restrict__ W, int ldw,
    const float* __restrict__ bias,
    float* __restrict__ out, int ldo,
    int nrows, int do_silu)
{
    __shared__ float As[16 * 128];
    __shared__ float Ws[16 * 128];

    const int colblk = blockIdx.y;
    W    += colblk * 128;
    bias += colblk * 128;
    out  += colblk * 128;

    const int row0 = blockIdx.x * 128;
    const int tid  = threadIdx.x;
    const int tx   = tid & 15;
    const int ty   = tid >> 4;

    float acc[8][8];
    #pragma unroll
    for (int i = 0; i < 8; i++)
        #pragma unroll
        for (int j = 0; j < 8; j++) acc[i][j] = 0.f;

    for (int k0 = 0; k0 < 128; k0 += 16) {
        __syncthreads();
        #pragma unroll
        for (int i = 0; i < 2; i++) {
            int lin = tid + i * 256;
            int r   = lin >> 2;
            int q   = lin & 3;
            float4 av = make_float4(0.f, 0.f, 0.f, 0.f);
            if (row0 + r < nrows)
                av = *(const float4*)(A + (size_t)(row0 + r) * 128 + k0 + q * 4);
            As[(q * 4 + 0) * 128 + r] = av.x;
            As[(q * 4 + 1) * 128 + r] = av.y;
            As[(q * 4 + 2) * 128 + r] = av.z;
            As[(q * 4 + 3) * 128 + r] = av.w;
        }
        #pragma unroll
        for (int i = 0; i < 2; i++) {
            int lin = tid + i * 256;
            int kr  = lin >> 5;
            int c4  = lin & 31;
            *(float4*)(Ws + kr * 128 + c4 * 4) =
                *(const float4*)(W + (size_t)(k0 + kr) * ldw + c4 * 4);
        }
        __syncthreads();

        #pragma unroll
        for (int kk = 0; kk < 16; kk++) {
            float4 a0 = *(const float4*)(As + kk * 128 + ty * 8);
            float4 a1 = *(const float4*)(As + kk * 128 + ty * 8 + 4);
            float4 b0 = *(const float4*)(Ws + kk * 128 + tx * 8);
            float4 b1 = *(const float4*)(Ws + kk * 128 + tx * 8 + 4);
            float av[8] = {a0.x, a0.y, a0.z, a0.w, a1.x, a1.y, a1.z, a1.w};
            float bv[8] = {b0.x, b0.y, b0.z, b0.w, b1.x, b1.y, b1.z, b1.w};
            #pragma unroll
            for (int i = 0; i < 8; i++)
                #pragma unroll
                for (int j = 0; j < 8; j++)
                    acc[i][j] = fmaf(av[i], bv[j], acc[i][j]);
        }
    }

    #pragma unroll
    for (int i = 0; i < 8; i++) {
        int r = row0 + ty * 8 + i;
        if (r < nrows) {
            #pragma unroll
            for (int j = 0; j < 8; j++) {
                float x = acc[i][j] + bias[tx * 8 + j];
                if (do_silu) x = x / (1.f + __expf(-x));
                out[(size_t)r * ldo + tx * 8 + j] = x;
            }
        }
    }
}

// ---------------------------------------------------------------------------
// Edge index helpers (runtime int64/int32 detection)
// ---------------------------------------------------------------------------
__device__ __forceinline__ bool edges_is64(const void* edges_raw) {
    const unsigned long long* e64 = (const unsigned long long*)edges_raw;
    return (e64[0] < 50000ULL) && (e64[1] < 50000ULL) &&
           (e64[2] < 50000ULL) && (e64[3] < 50000ULL);
}
__device__ __forceinline__ int edge_dst(const void* edges_raw, bool is64, int e) {
    if (is64) return (int)((const unsigned long long*)edges_raw)[2 * e];
    return ((const int*)edges_raw)[2 * e];
}
__device__ __forceinline__ int edge_src(const void* edges_raw, bool is64, int e) {
    if (is64) return (int)((const unsigned long long*)edges_raw)[2 * e + 1];
    return ((const int*)edges_raw)[2 * e + 1];
}

// ---------------------------------------------------------------------------
// CSR build: histogram -> scan -> fill
// ---------------------------------------------------------------------------
__global__ void hist_kernel(const void* __restrict__ edges_raw, int E) {
    const bool is64 = edges_is64(edges_raw);
    int e = blockIdx.x * blockDim.x + threadIdx.x;
    if (e < E) atomicAdd(&g_count[edge_dst(edges_raw, is64, e)], 1);
}

__global__ void __launch_bounds__(1024) scan_kernel() {
    __shared__ int partial[1024];
    const int CH = (NNODES + 1023) / 1024;   // 49
    const int t = threadIdx.x;
    const int base = t * CH;
    int sum = 0;
    for (int k = 0; k < CH; k++) {
        int idx = base + k;
        if (idx < NNODES) sum += g_count[idx];
    }
    partial[t] = sum;
    __syncthreads();
    for (int off = 1; off < 1024; off <<= 1) {
        int val = (t >= off) ? partial[t - off] : 0;
        __syncthreads();
        partial[t] += val;
        __syncthreads();
    }
    int run = (t > 0) ? partial[t - 1] : 0;
    for (int k = 0; k < CH; k++) {
        int idx = base + k;
        if (idx < NNODES) {
            int cval = g_count[idx];
            g_start[idx] = run;
            g_count[idx] = run;   // reset as fill cursor
            run += cval;
        }
    }
    if (t == 1023) g_start[NNODES] = partial[1023];
}

__global__ void fill_kernel(const void* __restrict__ edges_raw, int E) {
    const bool is64 = edges_is64(edges_raw);
    int e = blockIdx.x * blockDim.x + threadIdx.x;
    if (e < E) {
        int pos = atomicAdd(&g_count[edge_dst(edges_raw, is64, e)], 1);
        g_eid[pos] = e;
    }
}

// ---------------------------------------------------------------------------
// Per-edge basis: g_basis[e][n] = sin((n+1)x) * fc / r,  g_fc[e] = fc
// ---------------------------------------------------------------------------
__global__ void basis_kernel(const float* __restrict__ r_ij, int E) {
    int e = blockIdx.x * blockDim.x + threadIdx.x;
    if (e >= E) return;
    const float r = r_ij[e];
    const float x = (PI_F / R_CUT_F) * r;
    float s1, c1;
    __sincosf(x, &s1, &c1);
    const float fc = 0.5f * (c1 + 1.f);
    const float g  = fc / r;
    const float c2 = 2.f * c1;
    float sprev = 0.f, scur = s1;
    float* out = g_basis + (size_t)e * 20;
    #pragma unroll
    for (int n = 0; n < 20; n++) {
        out[n] = scur * g;
        const float snext = fmaf(c2, scur, -sprev);
        sprev = scur; scur = snext;
    }
    g_fc[e] = fc;
}

// ---------------------------------------------------------------------------
// Node gather: one block (128 threads) per node via grid-stride, channel-per-
// thread. No atomics; s/v residual fused into the final store.
// ---------------------------------------------------------------------------
__global__ void __launch_bounds__(128) node_gather(
    const void* __restrict__ edges_raw,
    const float* __restrict__ rhat,
    const float* __restrict__ spass,
    const float* __restrict__ v,
    const float* __restrict__ s,
    const float* __restrict__ Wr,
    const float* __restrict__ br,
    float* __restrict__ s_out,
    float* __restrict__ v_out,
    int N)
{
    const int c = threadIdx.x;
    const bool is64 = edges_is64(edges_raw);

    // Hoist this channel's 3 Wr columns (reused across all nodes of the block)
    float wdv[20], wds[20], wdr[20];
    #pragma unroll
    for (int n = 0; n < 20; n++) {
        wdv[n] = Wr[n * 384 + c];
        wds[n] = Wr[n * 384 + 128 + c];
        wdr[n] = Wr[n * 384 + 256 + c];
    }
    const float bdv = br[c], bds = br[128 + c], bdr = br[256 + c];

    for (int i = blockIdx.x; i < N; i += gridDim.x) {
        const int beg = g_start[i];
        const int end = g_start[i + 1];

        float accs = 0.f, av0 = 0.f, av1 = 0.f, av2 = 0.f;

        for (int t = beg; t < end; t++) {
            const int e   = g_eid[t];                 // uniform within block
            const int src = edge_src(edges_raw, is64, e);
            const float fc = g_fc[e];
            const float rx = rhat[3 * e + 0];
            const float ry = rhat[3 * e + 1];
            const float rz = rhat[3 * e + 2];

            // basis (20 floats, uniform address -> broadcast), as float4
            const float4* bb = (const float4*)(g_basis + (size_t)e * 20);
            float adv = 0.f, ads = 0.f, adr = 0.f;
            #pragma unroll
            for (int q = 0; q < 5; q++) {
                const float4 b4 = bb[q];
                const float bs[4] = {b4.x, b4.y, b4.z, b4.w};
                #pragma unroll
                for (int k = 0; k < 4; k++) {
                    const int n = q * 4 + k;
                    adv = fmaf(bs[k], wdv[n], adv);
                    ads = fmaf(bs[k], wds[n], ads);
                    adr = fmaf(bs[k], wdr[n], adr);
                }
            }
            adv = fmaf(bdv, fc, adv);
            ads = fmaf(bds, fc, ads);
            adr = fmaf(bdr, fc, adr);

            const float* spr = spass + (size_t)src * 384;
            const float dv = adv * spr[c];
            const float ds = ads * spr[128 + c];
            const float dr = adr * spr[256 + c];

            accs += ds;
            const float* vr = v + (size_t)src * 384;
            av0 = fmaf(vr[c],       dv, fmaf(rx, dr, av0));
            av1 = fmaf(vr[128 + c], dv, fmaf(ry, dr, av1));
            av2 = fmaf(vr[256 + c], dv, fmaf(rz, dr, av2));
        }

        s_out[(size_t)i * 128 + c] = s[(size_t)i * 128 + c] + accs;
        const float* vi = v     + (size_t)i * 384;
        float*       vo = v_out + (size_t)i * 384;
        vo[c]       = vi[c]       + av0;
        vo[128 + c] = vi[128 + c] + av1;
        vo[256 + c] = vi[256 + c] + av2;
    }
}

// ---------------------------------------------------------------------------
// kernel_launch
// Inputs: s, v, edges, r_ij, r_ij_normalized, W1, b1, W2, b2, Wr, br
// Output: [s_out (N*128) | v_out (N*3*128)] float32
// ---------------------------------------------------------------------------
extern "C" void kernel_launch(void* const* d_in, const int* in_sizes, int n_in,
                              void* d_out, int out_size)
{
    const float* s     = (const float*)d_in[0];
    const float* v     = (const float*)d_in[1];
    const void*  edges = d_in[2];
    const float* r_ij  = (const float*)d_in[3];
    const float* rhat  = (const float*)d_in[4];
    const float* W1    = (const float*)d_in[5];
    const float* b1    = (const float*)d_in[6];
    const float* W2    = (const float*)d_in[7];
    const float* b2    = (const float*)d_in[8];
    const float* Wr    = (const float*)d_in[9];
    const float* br    = (const float*)d_in[10];

    const int N = in_sizes[0] / CCH;      // 50000
    const int E = in_sizes[3];            // 400000

    float* out_s = (float*)d_out;
    float* out_v = out_s + (size_t)N * CCH;

    float* h_buf;
    float* sp_buf;
    int*   cnt_buf;
    cudaGetSymbolAddress((void**)&h_buf,  g_h);
    cudaGetSymbolAddress((void**)&sp_buf, g_spass);
    cudaGetSymbolAddress((void**)&cnt_buf, g_count);

    // ---- CSR build + per-edge basis (independent of GEMMs) ----
    cudaMemsetAsync(cnt_buf, 0, NNODES * sizeof(int));
    hist_kernel<<<(E + 255) / 256, 256>>>(edges, E);
    scan_kernel<<<1, 1024>>>();
    fill_kernel<<<(E + 255) / 256, 256>>>(edges, E);
    basis_kernel<<<(E + 255) / 256, 256>>>(r_ij, E);

    // ---- Node GEMMs ----
    {
        dim3 grid((N + 127) / 128, 1);
        gemm_v2<<<grid, 256>>>(s, W1, 128, b1, h_buf, 128, N, 1);
    }
    {
        dim3 grid((N + 127) / 128, 3);
        gemm_v2<<<grid, 256>>>(h_buf, W2, 384, b2, sp_buf, 384, N, 0);
    }

    // ---- Gather + residual ----
    node_gather<<<8192, 128>>>(edges, rhat, sp_buf, v, s, Wr, br,
                               out_s, out_v, N);
}

// round 5
// speedup vs baseline: 1.6160x; 1.6160x over previous
#include <cuda_runtime.h>
#include <math.h>

// Problem constants
#define NNODES 50000
#define EMAX   400000
#define CCH    128
#define PI_F   3.14159265358979323846f
#define R_CUT_F 5.0f

// Scratch (static device arrays: no allocation allowed)
__device__ float g_h[NNODES * CCH];          // silu(s@W1+b1)
__device__ float g_spass[NNODES * 3 * CCH];  // s_pass
__device__ float g_basis[EMAX * 20];         // sin(n x) * fc / r per edge
__device__ float g_fc[EMAX];                 // fcut per edge

// ---------------------------------------------------------------------------
// GEMM K=128 (unchanged from R2 — proven): 128x128 tile, 8x8 blocking.
// ---------------------------------------------------------------------------
__global__ void __launch_bounds__(256) gemm_v2(
    const float* __restrict__ A,
    const float* __restrict__ W, int ldw,
    const float* __restrict__ bias,
    float* __restrict__ out, int ldo,
    int nrows, int do_silu)
{
    __shared__ float As[16 * 128];
    __shared__ float Ws[16 * 128];

    const int colblk = blockIdx.y;
    W    += colblk * 128;
    bias += colblk * 128;
    out  += colblk * 128;

    const int row0 = blockIdx.x * 128;
    const int tid  = threadIdx.x;
    const int tx   = tid & 15;
    const int ty   = tid >> 4;

    float acc[8][8];
    #pragma unroll
    for (int i = 0; i < 8; i++)
        #pragma unroll
        for (int j = 0; j < 8; j++) acc[i][j] = 0.f;

    for (int k0 = 0; k0 < 128; k0 += 16) {
        __syncthreads();
        #pragma unroll
        for (int i = 0; i < 2; i++) {
            int lin = tid + i * 256;
            int r   = lin >> 2;
            int q   = lin & 3;
            float4 av = make_float4(0.f, 0.f, 0.f, 0.f);
            if (row0 + r < nrows)
                av = *(const float4*)(A + (size_t)(row0 + r) * 128 + k0 + q * 4);
            As[(q * 4 + 0) * 128 + r] = av.x;
            As[(q * 4 + 1) * 128 + r] = av.y;
            As[(q * 4 + 2) * 128 + r] = av.z;
            As[(q * 4 + 3) * 128 + r] = av.w;
        }
        #pragma unroll
        for (int i = 0; i < 2; i++) {
            int lin = tid + i * 256;
            int kr  = lin >> 5;
            int c4  = lin & 31;
            *(float4*)(Ws + kr * 128 + c4 * 4) =
                *(const float4*)(W + (size_t)(k0 + kr) * ldw + c4 * 4);
        }
        __syncthreads();

        #pragma unroll
        for (int kk = 0; kk < 16; kk++) {
            float4 a0 = *(const float4*)(As + kk * 128 + ty * 8);
            float4 a1 = *(const float4*)(As + kk * 128 + ty * 8 + 4);
            float4 b0 = *(const float4*)(Ws + kk * 128 + tx * 8);
            float4 b1 = *(const float4*)(Ws + kk * 128 + tx * 8 + 4);
            float av[8] = {a0.x, a0.y, a0.z, a0.w, a1.x, a1.y, a1.z, a1.w};
            float bv[8] = {b0.x, b0.y, b0.z, b0.w, b1.x, b1.y, b1.z, b1.w};
            #pragma unroll
            for (int i = 0; i < 8; i++)
                #pragma unroll
                for (int j = 0; j < 8; j++)
                    acc[i][j] = fmaf(av[i], bv[j], acc[i][j]);
        }
    }

    #pragma unroll
    for (int i = 0; i < 8; i++) {
        int r = row0 + ty * 8 + i;
        if (r < nrows) {
            #pragma unroll
            for (int j = 0; j < 8; j++) {
                float x = acc[i][j] + bias[tx * 8 + j];
                if (do_silu) x = x / (1.f + __expf(-x));
                out[(size_t)r * ldo + tx * 8 + j] = x;
            }
        }
    }
}

// ---------------------------------------------------------------------------
// Per-edge basis: g_basis[e][n] = sin((n+1)x) * fc / r,  g_fc[e] = fc
// ---------------------------------------------------------------------------
__global__ void basis_kernel(const float* __restrict__ r_ij, int E) {
    int e = blockIdx.x * blockDim.x + threadIdx.x;
    if (e >= E) return;
    const float r = r_ij[e];
    const float x = (PI_F / R_CUT_F) * r;
    float s1, c1;
    __sincosf(x, &s1, &c1);
    const float fc = 0.5f * (c1 + 1.f);
    const float g  = fc / r;
    const float c2 = 2.f * c1;
    float sprev = 0.f, scur = s1;
    float* out = g_basis + (size_t)e * 20;
    #pragma unroll
    for (int n = 0; n < 20; n++) {
        out[n] = scur * g;
        const float snext = fmaf(c2, scur, -sprev);
        sprev = scur; scur = snext;
    }
    g_fc[e] = fc;
}

// ---------------------------------------------------------------------------
// Vectorized global reduction: red.global.add.v4.f32 (sm_90+)
// ---------------------------------------------------------------------------
__device__ __forceinline__ void red_add_v4(float* p, float4 val) {
    asm volatile("red.global.add.v4.f32 [%0], {%1, %2, %3, %4};"
                 :: "l"(p), "f"(val.x), "f"(val.y), "f"(val.z), "f"(val.w)
                 : "memory");
}

// ---------------------------------------------------------------------------
// Edge scatter kernel: 96 threads = 3 warps (chunk 0=dv, 1=ds, 2=drep), each
// thread owns 4 channels. Contiguous edge range per block, 2 edges per
// iteration: all gathers issue before the FMA block (2x MLP + 2x FMA ILP).
// ---------------------------------------------------------------------------
__global__ void __launch_bounds__(96) edge_kernel(
    const void* __restrict__ edges_raw,
    const float* __restrict__ rhat,
    const float* __restrict__ spass,
    const float* __restrict__ v,
    const float* __restrict__ Wr,
    const float* __restrict__ br,
    float* __restrict__ s_out,
    float* __restrict__ v_out,
    int E, int per)
{
    const int ch   = threadIdx.x >> 5;
    const int lane = threadIdx.x & 31;

    // Hoist this thread's 4 Wr columns into registers
    float4 w4[20];
    #pragma unroll
    for (int n = 0; n < 20; n++)
        w4[n] = *(const float4*)(Wr + n * 384 + ch * 128 + lane * 4);
    const float4 b4 = *(const float4*)(br + ch * 128 + lane * 4);

    // int64 vs int32 edge indices
    const unsigned long long* e64 = (const unsigned long long*)edges_raw;
    const bool is64 = (e64[0] < 50000ULL) && (e64[1] < 50000ULL) &&
                      (e64[2] < 50000ULL) && (e64[3] < 50000ULL);
    const ulonglong2* E64 = (const ulonglong2*)edges_raw;
    const int2*       E32 = (const int2*)edges_raw;

    const int e0 = blockIdx.x * per;
    const int e1 = (e0 + per < E) ? (e0 + per) : E;

    for (int e = e0; e < e1; e += 2) {
        const bool hasB = (e + 1 < e1);
        const int  eB   = hasB ? (e + 1) : e;

        // ---- index loads ----
        int dstA, srcA, dstB, srcB;
        if (is64) {
            ulonglong2 pa = E64[e];  dstA = (int)pa.x; srcA = (int)pa.y;
            ulonglong2 pb = E64[eB]; dstB = (int)pb.x; srcB = (int)pb.y;
        } else {
            int2 pa = E32[e];  dstA = pa.x; srcA = pa.y;
            int2 pb = E32[eB]; dstB = pb.x; srcB = pb.y;
        }

        // ---- long-latency gathers, both edges up front ----
        const float fcA = g_fc[e];
        const float fcB = g_fc[eB];
        const float4 spA = ((const float4*)(spass + (size_t)srcA * 384))[ch * 32 + lane];
        const float4 spB = ((const float4*)(spass + (size_t)srcB * 384))[ch * 32 + lane];

        float4 vA0, vA1, vA2, vB0, vB1, vB2;
        float rxA = 0.f, ryA = 0.f, rzA = 0.f, rxB = 0.f, ryB = 0.f, rzB = 0.f;
        if (ch == 0) {
            const float4* vrA = (const float4*)(v + (size_t)srcA * 384);
            const float4* vrB = (const float4*)(v + (size_t)srcB * 384);
            vA0 = vrA[lane]; vA1 = vrA[32 + lane]; vA2 = vrA[64 + lane];
            vB0 = vrB[lane]; vB1 = vrB[32 + lane]; vB2 = vrB[64 + lane];
        } else if (ch == 2) {
            rxA = rhat[3 * e + 0];  ryA = rhat[3 * e + 1];  rzA = rhat[3 * e + 2];
            rxB = rhat[3 * eB + 0]; ryB = rhat[3 * eB + 1]; rzB = rhat[3 * eB + 2];
        }

        // ---- dot products (basis is contiguous/broadcast) ----
        const float4* bbA = (const float4*)(g_basis + (size_t)e  * 20);
        const float4* bbB = (const float4*)(g_basis + (size_t)eB * 20);
        float4 accA = make_float4(0.f, 0.f, 0.f, 0.f);
        float4 accB = make_float4(0.f, 0.f, 0.f, 0.f);
        #pragma unroll
        for (int q = 0; q < 5; q++) {
            const float4 bA = bbA[q];
            const float4 bB = bbB[q];
            const float bsA[4] = {bA.x, bA.y, bA.z, bA.w};
            const float bsB[4] = {bB.x, bB.y, bB.z, bB.w};
            #pragma unroll
            for (int k = 0; k < 4; k++) {
                const float4 w = w4[q * 4 + k];
                accA.x = fmaf(bsA[k], w.x, accA.x);
                accA.y = fmaf(bsA[k], w.y, accA.y);
                accA.z = fmaf(bsA[k], w.z, accA.z);
                accA.w = fmaf(bsA[k], w.w, accA.w);
                accB.x = fmaf(bsB[k], w.x, accB.x);
                accB.y = fmaf(bsB[k], w.y, accB.y);
                accB.z = fmaf(bsB[k], w.z, accB.z);
                accB.w = fmaf(bsB[k], w.w, accB.w);
            }
        }

        float4 coefA, coefB;
        coefA.x = fmaf(b4.x, fcA, accA.x) * spA.x;
        coefA.y = fmaf(b4.y, fcA, accA.y) * spA.y;
        coefA.z = fmaf(b4.z, fcA, accA.z) * spA.z;
        coefA.w = fmaf(b4.w, fcA, accA.w) * spA.w;
        coefB.x = fmaf(b4.x, fcB, accB.x) * spB.x;
        coefB.y = fmaf(b4.y, fcB, accB.y) * spB.y;
        coefB.z = fmaf(b4.z, fcB, accB.z) * spB.z;
        coefB.w = fmaf(b4.w, fcB, accB.w) * spB.w;

        // ---- scatter ----
        if (ch == 0) {
            float* voA = v_out + (size_t)dstA * 384;
            float4 o;
            o.x = vA0.x * coefA.x; o.y = vA0.y * coefA.y; o.z = vA0.z * coefA.z; o.w = vA0.w * coefA.w;
            red_add_v4(voA + lane * 4, o);
            o.x = vA1.x * coefA.x; o.y = vA1.y * coefA.y; o.z = vA1.z * coefA.z; o.w = vA1.w * coefA.w;
            red_add_v4(voA + 128 + lane * 4, o);
            o.x = vA2.x * coefA.x; o.y = vA2.y * coefA.y; o.z = vA2.z * coefA.z; o.w = vA2.w * coefA.w;
            red_add_v4(voA + 256 + lane * 4, o);
            if (hasB) {
                float* voB = v_out + (size_t)dstB * 384;
                o.x = vB0.x * coefB.x; o.y = vB0.y * coefB.y; o.z = vB0.z * coefB.z; o.w = vB0.w * coefB.w;
                red_add_v4(voB + lane * 4, o);
                o.x = vB1.x * coefB.x; o.y = vB1.y * coefB.y; o.z = vB1.z * coefB.z; o.w = vB1.w * coefB.w;
                red_add_v4(voB + 128 + lane * 4, o);
                o.x = vB2.x * coefB.x; o.y = vB2.y * coefB.y; o.z = vB2.z * coefB.z; o.w = vB2.w * coefB.w;
                red_add_v4(voB + 256 + lane * 4, o);
            }
        } else if (ch == 1) {
            red_add_v4(s_out + (size_t)dstA * 128 + lane * 4, coefA);
            if (hasB)
                red_add_v4(s_out + (size_t)dstB * 128 + lane * 4, coefB);
        } else {
            float* voA = v_out + (size_t)dstA * 384;
            float4 o;
            o.x = rxA * coefA.x; o.y = rxA * coefA.y; o.z = rxA * coefA.z; o.w = rxA * coefA.w;
            red_add_v4(voA + lane * 4, o);
            o.x = ryA * coefA.x; o.y = ryA * coefA.y; o.z = ryA * coefA.z; o.w = ryA * coefA.w;
            red_add_v4(voA + 128 + lane * 4, o);
            o.x = rzA * coefA.x; o.y = rzA * coefA.y; o.z = rzA * coefA.z; o.w = rzA * coefA.w;
            red_add_v4(voA + 256 + lane * 4, o);
            if (hasB) {
                float* voB = v_out + (size_t)dstB * 384;
                o.x = rxB * coefB.x; o.y = rxB * coefB.y; o.z = rxB * coefB.z; o.w = rxB * coefB.w;
                red_add_v4(voB + lane * 4, o);
                o.x = ryB * coefB.x; o.y = ryB * coefB.y; o.z = ryB * coefB.z; o.w = ryB * coefB.w;
                red_add_v4(voB + 128 + lane * 4, o);
                o.x = rzB * coefB.x; o.y = rzB * coefB.y; o.z = rzB * coefB.z; o.w = rzB * coefB.w;
                red_add_v4(voB + 256 + lane * 4, o);
            }
        }
    }
}

// ---------------------------------------------------------------------------
// kernel_launch
// Inputs: s, v, edges, r_ij, r_ij_normalized, W1, b1, W2, b2, Wr, br
// Output: [s_out (N*128) | v_out (N*3*128)] float32
// ---------------------------------------------------------------------------
extern "C" void kernel_launch(void* const* d_in, const int* in_sizes, int n_in,
                              void* d_out, int out_size)
{
    const float* s     = (const float*)d_in[0];
    const float* v     = (const float*)d_in[1];
    const void*  edges = d_in[2];
    const float* r_ij  = (const float*)d_in[3];
    const float* rhat  = (const float*)d_in[4];
    const float* W1    = (const float*)d_in[5];
    const float* b1    = (const float*)d_in[6];
    const float* W2    = (const float*)d_in[7];
    const float* b2    = (const float*)d_in[8];
    const float* Wr    = (const float*)d_in[9];
    const float* br    = (const float*)d_in[10];

    const int N = in_sizes[0] / CCH;      // 50000
    const int E = in_sizes[3];            // 400000

    float* out_s = (float*)d_out;
    float* out_v = out_s + (size_t)N * CCH;

    float* h_buf;
    float* sp_buf;
    cudaGetSymbolAddress((void**)&h_buf,  g_h);
    cudaGetSymbolAddress((void**)&sp_buf, g_spass);

    // Seed outputs with s and v (d_out is poisoned)
    cudaMemcpyAsync(out_s, s, (size_t)N * CCH * sizeof(float),
                    cudaMemcpyDeviceToDevice);
    cudaMemcpyAsync(out_v, v, (size_t)N * 3 * CCH * sizeof(float),
                    cudaMemcpyDeviceToDevice);

    // Per-edge basis (independent of GEMMs)
    basis_kernel<<<(E + 255) / 256, 256>>>(r_ij, E);

    // Node GEMMs
    {
        dim3 grid((N + 127) / 128, 1);
        gemm_v2<<<grid, 256>>>(s, W1, 128, b1, h_buf, 128, N, 1);
    }
    {
        dim3 grid((N + 127) / 128, 3);
        gemm_v2<<<grid, 256>>>(h_buf, W2, 384, b2, sp_buf, 384, N, 0);
    }

    // Edge message + scatter
    {
        const int grid = 4096;
        int per = (E + grid - 1) / grid;
        per = (per + 1) & ~1;   // even per-block count
        edge_kernel<<<grid, 96>>>(edges, rhat, sp_buf, v,
                                  Wr, br, out_s, out_v, E, per);
    }
}